// round 2
// baseline (speedup 1.0000x reference)
#include <cuda_runtime.h>
#include <math.h>

namespace {

constexpr int B = 32, S = 196, T = 64, H = 1024, V = 32000;
constexpr int KQ = 16;   // k-splits for q GEMM (chunks of 64 over K=1024)
constexpr int KG = 12;   // k-splits for gates GEMM (chunks of 256 over K=3072)

typedef unsigned long long ull;

// ---------------- device scratch (static: no allocations allowed) ----------
__device__ __align__(16) float g_h[B * H];
__device__ __align__(16) float g_c[B * H];
__device__ __align__(16) float g_ctx[B * H];
__device__ __align__(16) float g_qpart[KQ * B * H];
__device__ __align__(16) float g_gpart[KG * B * 4 * H];
__device__ __align__(16) float g_Hall[(size_t)T * B * H];   // Hall[m][k], m = t*B + b

// ---------------- packed f32x2 + async-copy helpers ------------------------
__device__ __forceinline__ ull pack2(float x, float y) {
    ull r;
    asm("mov.b64 %0, {%1, %2};" : "=l"(r)
        : "r"(__float_as_uint(x)), "r"(__float_as_uint(y)));
    return r;
}
__device__ __forceinline__ void ffma2(ull &d, ull a, ull b) {
    asm("fma.rn.f32x2 %0, %1, %2, %0;" : "+l"(d) : "l"(a), "l"(b));
}
__device__ __forceinline__ void unpack2(ull v, float &x, float &y) {
    unsigned lo, hi;
    asm("mov.b64 {%0, %1}, %2;" : "=r"(lo), "=r"(hi) : "l"(v));
    x = __uint_as_float(lo);
    y = __uint_as_float(hi);
}
__device__ __forceinline__ unsigned smaddr(const void* p) {
    return (unsigned)__cvta_generic_to_shared(p);
}
__device__ __forceinline__ void cp16(unsigned s, const void* g) {
    asm volatile("cp.async.cg.shared.global [%0], [%1], 16;\n" :: "r"(s), "l"(g));
}
__device__ __forceinline__ void cp_commit() {
    asm volatile("cp.async.commit_group;\n");
}
template <int N>
__device__ __forceinline__ void cp_wait() {
    asm volatile("cp.async.wait_group %0;\n" :: "n"(N));
}

// ---------------- init: zero h, c ------------------------------------------
__global__ void k_init() {
    int i = blockIdx.x * 256 + threadIdx.x;
    if (i < B * H) { g_h[i] = 0.f; g_c[i] = 0.f; }
}

// ---------------- q = h @ attn_W.T  (M=32, N=1024, K=1024, k-split) --------
__global__ void k_q(const float* __restrict__ attn_W) {
    const int n0 = blockIdx.x * 64;
    const int ks = blockIdx.y;
    const int k0 = ks * 64;
    const int tid = threadIdx.x;
    __shared__ float hs[B][68];
    __shared__ float Ws[64][68];

    for (int idx = tid; idx < B * 64; idx += 256) {
        int b = idx >> 6, k = idx & 63;
        hs[b][k] = g_h[b * H + k0 + k];
    }
    for (int idx = tid; idx < 64 * 64; idx += 256) {
        int n = idx >> 6, k = idx & 63;
        Ws[k][n] = attn_W[(size_t)(n0 + n) * H + k0 + k];
    }
    __syncthreads();

    const int bg = tid >> 4;
    const int ng = tid & 15;
    const int b0 = bg * 2, nn = ng * 4;
    float acc[2][4] = {};
#pragma unroll 8
    for (int k = 0; k < 64; k++) {
        float a0 = hs[b0][k], a1 = hs[b0 + 1][k];
        float4 w = *(const float4*)&Ws[k][nn];
        acc[0][0] += a0 * w.x; acc[0][1] += a0 * w.y;
        acc[0][2] += a0 * w.z; acc[0][3] += a0 * w.w;
        acc[1][0] += a1 * w.x; acc[1][1] += a1 * w.y;
        acc[1][2] += a1 * w.z; acc[1][3] += a1 * w.w;
    }
    float* qp = g_qpart + ks * (B * H);
#pragma unroll
    for (int i = 0; i < 2; i++)
#pragma unroll
        for (int j = 0; j < 4; j++)
            qp[(b0 + i) * H + n0 + nn + j] = acc[i][j];
}

// ---------------- attention: scores -> softmax -> ctx ----------------------
__global__ void k_attn(const float* __restrict__ memory) {
    const int b = blockIdx.x;
    const int tid = threadIdx.x;
    __shared__ float q[H];
    __shared__ float sc[224];
    __shared__ float red[256];

    for (int j = tid; j < H; j += 256) {
        float s = 0.f;
#pragma unroll
        for (int p = 0; p < KQ; p++) s += g_qpart[p * (B * H) + b * H + j];
        q[j] = s;
    }
    __syncthreads();

    const float* mb = memory + (size_t)b * S * H;
    const int warp = tid >> 5, lane = tid & 31;
    for (int s = warp; s < S; s += 8) {
        const float* ms = mb + (size_t)s * H;
        float acc = 0.f;
        for (int k = lane; k < H; k += 32) acc += q[k] * ms[k];
#pragma unroll
        for (int o = 16; o; o >>= 1) acc += __shfl_xor_sync(0xffffffffu, acc, o);
        if (lane == 0) sc[s] = acc;
    }
    __syncthreads();

    red[tid] = (tid < S) ? sc[tid] : -1e30f;
    __syncthreads();
    for (int step = 128; step; step >>= 1) {
        if (tid < step) red[tid] = fmaxf(red[tid], red[tid + step]);
        __syncthreads();
    }
    float mx = red[0];
    __syncthreads();
    float e = (tid < S) ? expf(sc[tid] - mx) : 0.f;
    if (tid < S) sc[tid] = e;
    red[tid] = e;
    __syncthreads();
    for (int step = 128; step; step >>= 1) {
        if (tid < step) red[tid] += red[tid + step];
        __syncthreads();
    }
    float inv = 1.f / red[0];

    float a0 = 0.f, a1 = 0.f, a2 = 0.f, a3 = 0.f;
    for (int s = 0; s < S; s++) {
        float w = sc[s];
        const float* ms = mb + (size_t)s * H + tid;
        a0 += w * ms[0];
        a1 += w * ms[256];
        a2 += w * ms[512];
        a3 += w * ms[768];
    }
    g_ctx[b * H + tid]       = a0 * inv;
    g_ctx[b * H + tid + 256] = a1 * inv;
    g_ctx[b * H + tid + 512] = a2 * inv;
    g_ctx[b * H + tid + 768] = a3 * inv;
}

// ---------------- gates GEMM v2: cp.async double-buffered ------------------
// x = [emb_t | ctx | h], K=3072; grid (64 n-tiles of 64, 12 k-chunks of 256)
// block = 128 threads; per thread 4b x 4n, f32x2 packed along k.
__global__ void __launch_bounds__(128) k_gates(const float* __restrict__ W_ih,
                                               const float* __restrict__ W_hh,
                                               const float* __restrict__ emb_table,
                                               const int* __restrict__ captions, int t) {
    const int n0 = blockIdx.x * 64;
    const int c  = blockIdx.y;           // 0..3 emb, 4..7 ctx (W_ih), 8..11 h (W_hh)
    const int tid = threadIdx.x;
    __shared__ float Ws[2][64][36];      // [buf][n][k] 32k + pad4, 16B-aligned rows
    __shared__ float xs[2][32][36];      // [buf][b][k]
    __shared__ const float* xptr[32];

    const float* W; int ldw, col0;
    if (c < 8) { W = W_ih; ldw = 2 * H; col0 = c * 256; }
    else       { W = W_hh; ldw = H;     col0 = (c - 8) * 256; }

    if (tid < 32) {
        int b = tid;
        const float* p;
        if (c < 4)      p = emb_table + (size_t)captions[b * T + t] * H + c * 256;
        else if (c < 8) p = g_ctx + b * H + (c - 4) * 256;
        else            p = g_h + b * H + (c - 8) * 256;
        xptr[b] = p;
    }
    __syncthreads();

    const float* xp0 = xptr[(tid      ) >> 3];     // for xs fill r=0
    const float* xp1 = xptr[(tid + 128) >> 3];     // for xs fill r=1

    // prefetch one 32-k sub-chunk into buffer `buf`
    auto prefetch = [&](int buf, int k0) {
#pragma unroll
        for (int r = 0; r < 4; r++) {
            int idx = tid + 128 * r;
            int n = idx >> 3, k4 = (idx & 7) * 4;
            cp16(smaddr(&Ws[buf][n][k4]),
                 W + (size_t)(n0 + n) * ldw + col0 + k0 + k4);
        }
        {
            int k4 = (tid & 7) * 4;
            cp16(smaddr(&xs[buf][tid >> 3][k4]), xp0 + k0 + k4);
            cp16(smaddr(&xs[buf][(tid + 128) >> 3][k4]), xp1 + k0 + k4);
        }
    };

    const int ng = tid & 15;      // n = n0 + ng + 16*j
    const int bg = tid >> 4;      // b = bg*4 + i
    ull acc[4][4] = {};

    prefetch(0, 0);
    cp_commit();

#pragma unroll 1
    for (int s = 0; s < 8; s++) {
        if (s < 7) { prefetch((s + 1) & 1, (s + 1) * 32); cp_commit(); }
        if (s < 7) cp_wait<1>(); else cp_wait<0>();
        __syncthreads();
        const int buf = s & 1;
#pragma unroll
        for (int k = 0; k < 32; k += 4) {
            ulonglong2 xv[4], wv[4];
#pragma unroll
            for (int i = 0; i < 4; i++)
                xv[i] = *(const ulonglong2*)&xs[buf][bg * 4 + i][k];
#pragma unroll
            for (int j = 0; j < 4; j++)
                wv[j] = *(const ulonglong2*)&Ws[buf][ng + 16 * j][k];
#pragma unroll
            for (int i = 0; i < 4; i++)
#pragma unroll
                for (int j = 0; j < 4; j++) {
                    ffma2(acc[i][j], xv[i].x, wv[j].x);
                    ffma2(acc[i][j], xv[i].y, wv[j].y);
                }
        }
        __syncthreads();
    }

    float* gp = g_gpart + c * (B * 4 * H);
#pragma unroll
    for (int i = 0; i < 4; i++) {
        int b = bg * 4 + i;
#pragma unroll
        for (int j = 0; j < 4; j++) {
            float lo, hi;
            unpack2(acc[i][j], lo, hi);
            gp[b * 4 * H + n0 + ng + 16 * j] = lo + hi;
        }
    }
}

// ---------------- LSTM cell pointwise + state update + Hall store ----------
__global__ void k_cell(const float* __restrict__ b_ih, const float* __restrict__ b_hh, int t) {
    int idx = blockIdx.x * 256 + threadIdx.x;
    if (idx >= B * H) return;
    int b = idx >> 10, j = idx & (H - 1);
    float gi = 0.f, gf = 0.f, gg = 0.f, go = 0.f;
#pragma unroll
    for (int p = 0; p < KG; p++) {
        const float* base = g_gpart + p * (B * 4 * H) + b * 4 * H;
        gi += base[j];
        gf += base[j + H];
        gg += base[j + 2 * H];
        go += base[j + 3 * H];
    }
    gi += b_ih[j] + b_hh[j];
    gf += b_ih[j + H] + b_hh[j + H];
    gg += b_ih[j + 2 * H] + b_hh[j + 2 * H];
    go += b_ih[j + 3 * H] + b_hh[j + 3 * H];
    float iv = 1.f / (1.f + expf(-gi));
    float fv = 1.f / (1.f + expf(-gf));
    float gv = tanhf(gg);
    float ov = 1.f / (1.f + expf(-go));
    float cn = fv * g_c[idx] + iv * gv;
    float hn = ov * tanhf(cn);
    g_c[idx] = cn;
    g_h[idx] = hn;
    g_Hall[((size_t)t * B + b) * H + j] = hn;   // m = t*B + b
}

// ---------------- batched logits GEMM: Hall[2048,1024] @ W_out.T -----------
// 128x128 tile, 8x8 per thread, f32x2 along n, register-prefetch pipeline
__global__ void __launch_bounds__(256) k_logits(const float* __restrict__ Wout,
                                                const float* __restrict__ bout,
                                                float* __restrict__ out) {
    const int n0 = blockIdx.x * 128;
    const int m0 = blockIdx.y * 128;
    const int tid = threadIdx.x;
    __shared__ float As[8][128];   // As[k][m]
    __shared__ float Bs[8][128];   // Bs[k][n]

    const int lm = tid >> 1, lk = (tid & 1) * 4;
    const float* Ap = g_Hall + (size_t)(m0 + lm) * H + lk;
    const float* Bp = Wout   + (size_t)(n0 + lm) * H + lk;

    const int ty = tid >> 4, tx = tid & 15;
    const int ms = ty * 8, ns = tx * 8;
    ull acc[8][4] = {};

    float4 av = *(const float4*)(Ap);
    float4 bv = *(const float4*)(Bp);

    for (int k0 = 0; k0 < H; k0 += 8) {
        __syncthreads();
        As[lk][lm] = av.x; As[lk + 1][lm] = av.y; As[lk + 2][lm] = av.z; As[lk + 3][lm] = av.w;
        Bs[lk][lm] = bv.x; Bs[lk + 1][lm] = bv.y; Bs[lk + 2][lm] = bv.z; Bs[lk + 3][lm] = bv.w;
        __syncthreads();
        if (k0 + 8 < H) {
            av = *(const float4*)(Ap + k0 + 8);
            bv = *(const float4*)(Bp + k0 + 8);
        }
#pragma unroll
        for (int kk = 0; kk < 8; kk++) {
            float4 a0 = *(const float4*)&As[kk][ms];
            float4 a1 = *(const float4*)&As[kk][ms + 4];
            ulonglong2 b0 = *(const ulonglong2*)&Bs[kk][ns];
            ulonglong2 b1 = *(const ulonglong2*)&Bs[kk][ns + 4];
            float a[8] = {a0.x, a0.y, a0.z, a0.w, a1.x, a1.y, a1.z, a1.w};
            ull bp[4]  = {b0.x, b0.y, b1.x, b1.y};
#pragma unroll
            for (int i = 0; i < 8; i++) {
                ull ap = pack2(a[i], a[i]);
                ffma2(acc[i][0], ap, bp[0]);
                ffma2(acc[i][1], ap, bp[1]);
                ffma2(acc[i][2], ap, bp[2]);
                ffma2(acc[i][3], ap, bp[3]);
            }
        }
    }
#pragma unroll
    for (int i = 0; i < 8; i++) {
        int m  = m0 + ms + i;
        int tt = m >> 5, b = m & 31;                        // m = t*B + b
        float* orow = out + ((size_t)(b * T + tt)) * V + n0 + ns;
        const float* br = bout + n0 + ns;
#pragma unroll
        for (int j = 0; j < 4; j++) {
            float vx, vy;
            unpack2(acc[i][j], vx, vy);
            float2 o2 = make_float2(vx + br[2 * j], vy + br[2 * j + 1]);
            *(float2*)&orow[2 * j] = o2;
        }
    }
}

// ---------------- final h, c copy into out tail ----------------------------
__global__ void k_final(float* __restrict__ dst) {
    int i = blockIdx.x * 256 + threadIdx.x;
    if (i < B * H) {
        dst[i]         = g_h[i];
        dst[B * H + i] = g_c[i];
    }
}

} // namespace

extern "C" void kernel_launch(void* const* d_in, const int* in_sizes, int n_in,
                              void* d_out, int out_size) {
    const float* memory   = (const float*)d_in[0];
    const int*   captions = (const int*)d_in[1];
    const float* emb      = (const float*)d_in[2];
    const float* attn_W   = (const float*)d_in[3];
    const float* W_ih     = (const float*)d_in[4];
    const float* W_hh     = (const float*)d_in[5];
    const float* b_ih     = (const float*)d_in[6];
    const float* b_hh     = (const float*)d_in[7];
    const float* W_out    = (const float*)d_in[8];
    const float* b_out    = (const float*)d_in[9];
    float* out = (float*)d_out;

    k_init<<<(B * H + 255) / 256, 256>>>();
    for (int t = 0; t < T; t++) {
        k_q<<<dim3(16, KQ), 256>>>(attn_W);
        k_attn<<<B, 256>>>(memory);
        k_gates<<<dim3(64, KG), 128>>>(W_ih, W_hh, emb, captions, t);
        k_cell<<<(B * H + 255) / 256, 256>>>(b_ih, b_hh, t);
    }
    k_logits<<<dim3(V / 128, (T * B) / 128), 256>>>(W_out, b_out, out);
    if (out_size >= B * T * V + 2 * B * H)
        k_final<<<(B * H + 255) / 256, 256>>>(out + (size_t)B * T * V);
}

// round 3
// speedup vs baseline: 1.0872x; 1.0872x over previous
#include <cuda_runtime.h>
#include <math.h>

namespace {

constexpr int B = 32, S = 196, T = 64, H = 1024, V = 32000;
constexpr int KQ = 16;   // k-splits for q GEMM
constexpr int KG = 32;   // k-splits for gates GEMM (chunks of 64 over K=2048)

typedef unsigned long long ull;

// ---------------- device scratch -------------------------------------------
__device__ __align__(16) float g_h[B * H];
__device__ __align__(16) float g_c[B * H];
__device__ __align__(16) float g_ctx[B * H];
__device__ __align__(16) float g_qpart[KQ * B * H];
__device__ __align__(16) float g_gpart[KG * B * 4 * H];
__device__ __align__(16) float g_gemb[(size_t)T * B * 4 * H];  // precomputed emb-gates + biases
__device__ __align__(16) float g_Hall[(size_t)T * B * H];      // Hall[m][k], m = t*B + b

// ---------------- helpers --------------------------------------------------
__device__ __forceinline__ void ffma2(ull &d, ull a, ull b) {
    asm("fma.rn.f32x2 %0, %1, %2, %0;" : "+l"(d) : "l"(a), "l"(b));
}
__device__ __forceinline__ void unpack2(ull v, float &x, float &y) {
    unsigned lo, hi;
    asm("mov.b64 {%0, %1}, %2;" : "=r"(lo), "=r"(hi) : "l"(v));
    x = __uint_as_float(lo);
    y = __uint_as_float(hi);
}
__device__ __forceinline__ unsigned smaddr(const void* p) {
    return (unsigned)__cvta_generic_to_shared(p);
}
__device__ __forceinline__ void cp16(unsigned s, const void* g) {
    asm volatile("cp.async.cg.shared.global [%0], [%1], 16;\n" :: "r"(s), "l"(g));
}
__device__ __forceinline__ void cp_commit() {
    asm volatile("cp.async.commit_group;\n");
}
template <int N>
__device__ __forceinline__ void cp_wait() {
    asm volatile("cp.async.wait_group %0;\n" :: "n"(N));
}

// ---------------- init -----------------------------------------------------
__global__ void k_init() {
    int i = blockIdx.x * 256 + threadIdx.x;
    if (i < B * H) { g_h[i] = 0.f; g_c[i] = 0.f; }
}

// ---------------- q = h @ attn_W.T  (unchanged) ----------------------------
__global__ void k_q(const float* __restrict__ attn_W) {
    const int n0 = blockIdx.x * 64;
    const int ks = blockIdx.y;
    const int k0 = ks * 64;
    const int tid = threadIdx.x;
    __shared__ float hs[B][68];
    __shared__ float Ws[64][68];

    for (int idx = tid; idx < B * 64; idx += 256) {
        int b = idx >> 6, k = idx & 63;
        hs[b][k] = g_h[b * H + k0 + k];
    }
    for (int idx = tid; idx < 64 * 64; idx += 256) {
        int n = idx >> 6, k = idx & 63;
        Ws[k][n] = attn_W[(size_t)(n0 + n) * H + k0 + k];
    }
    __syncthreads();

    const int bg = tid >> 4;
    const int ng = tid & 15;
    const int b0 = bg * 2, nn = ng * 4;
    float acc[2][4] = {};
#pragma unroll 8
    for (int k = 0; k < 64; k++) {
        float a0 = hs[b0][k], a1 = hs[b0 + 1][k];
        float4 w = *(const float4*)&Ws[k][nn];
        acc[0][0] += a0 * w.x; acc[0][1] += a0 * w.y;
        acc[0][2] += a0 * w.z; acc[0][3] += a0 * w.w;
        acc[1][0] += a1 * w.x; acc[1][1] += a1 * w.y;
        acc[1][2] += a1 * w.z; acc[1][3] += a1 * w.w;
    }
    float* qp = g_qpart + ks * (B * H);
#pragma unroll
    for (int i = 0; i < 2; i++)
#pragma unroll
        for (int j = 0; j < 4; j++)
            qp[(b0 + i) * H + n0 + nn + j] = acc[i][j];
}

// ---------------- attention (unchanged) ------------------------------------
__global__ void k_attn(const float* __restrict__ memory) {
    const int b = blockIdx.x;
    const int tid = threadIdx.x;
    __shared__ float q[H];
    __shared__ float sc[224];
    __shared__ float red[256];

    for (int j = tid; j < H; j += 256) {
        float s = 0.f;
#pragma unroll
        for (int p = 0; p < KQ; p++) s += g_qpart[p * (B * H) + b * H + j];
        q[j] = s;
    }
    __syncthreads();

    const float* mb = memory + (size_t)b * S * H;
    const int warp = tid >> 5, lane = tid & 31;
    for (int s = warp; s < S; s += 8) {
        const float* ms = mb + (size_t)s * H;
        float acc = 0.f;
        for (int k = lane; k < H; k += 32) acc += q[k] * ms[k];
#pragma unroll
        for (int o = 16; o; o >>= 1) acc += __shfl_xor_sync(0xffffffffu, acc, o);
        if (lane == 0) sc[s] = acc;
    }
    __syncthreads();

    red[tid] = (tid < S) ? sc[tid] : -1e30f;
    __syncthreads();
    for (int step = 128; step; step >>= 1) {
        if (tid < step) red[tid] = fmaxf(red[tid], red[tid + step]);
        __syncthreads();
    }
    float mx = red[0];
    __syncthreads();
    float e = (tid < S) ? expf(sc[tid] - mx) : 0.f;
    if (tid < S) sc[tid] = e;
    red[tid] = e;
    __syncthreads();
    for (int step = 128; step; step >>= 1) {
        if (tid < step) red[tid] += red[tid + step];
        __syncthreads();
    }
    float inv = 1.f / red[0];

    float a0 = 0.f, a1 = 0.f, a2 = 0.f, a3 = 0.f;
    for (int s = 0; s < S; s++) {
        float w = sc[s];
        const float* ms = mb + (size_t)s * H + tid;
        a0 += w * ms[0];
        a1 += w * ms[256];
        a2 += w * ms[512];
        a3 += w * ms[768];
    }
    g_ctx[b * H + tid]       = a0 * inv;
    g_ctx[b * H + tid + 256] = a1 * inv;
    g_ctx[b * H + tid + 512] = a2 * inv;
    g_ctx[b * H + tid + 768] = a3 * inv;
}

// ---------------- shared GEMM core: 128m x 64n tile, K=1024 ----------------
// MODE 0: emb-gates precompute  (A = gathered emb rows, out = g_gemb + b_ih + b_hh)
// MODE 1: logits                (A = g_Hall rows,       out = logits + b_out)
// 256 threads, per thread 8m x 4n, k-packed f32x2, KT=16 double-buffered.
template <int MODE>
__global__ void __launch_bounds__(256) k_gemm(const float* __restrict__ Bmat, int ldb,
                                              const float* __restrict__ bias1,
                                              const float* __restrict__ bias2,
                                              float* __restrict__ outp,
                                              const int* __restrict__ captions,
                                              const float* __restrict__ emb_table) {
    const int m0 = blockIdx.x * 128;
    const int n0 = blockIdx.y * 64;
    const int tid = threadIdx.x;
    __shared__ float As[2][128][20];
    __shared__ float Bs[2][64][20];
    __shared__ const float* arow[128];

    if (tid < 128) {
        int m = m0 + tid;
        if (MODE == 0) {
            int t = m >> 5, b = m & 31;
            arow[tid] = emb_table + (size_t)captions[b * T + t] * H;
        } else {
            arow[tid] = g_Hall + (size_t)m * H;
        }
    }
    __syncthreads();

    auto stage = [&](int buf, int k0) {
        // As: 128 rows x 16 k = 512 cp16 -> 2 per thread
#pragma unroll
        for (int r = 0; r < 2; r++) {
            int idx = r * 256 + tid;
            int row = idx >> 2, k4 = (idx & 3) * 4;
            cp16(smaddr(&As[buf][row][k4]), arow[row] + k0 + k4);
        }
        // Bs: 64 rows x 16 k = 256 cp16 -> 1 per thread
        {
            int row = tid >> 2, k4 = (tid & 3) * 4;
            cp16(smaddr(&Bs[buf][row][k4]), Bmat + (size_t)(n0 + row) * ldb + k0 + k4);
        }
    };

    const int mg = tid >> 4;   // 16 m-groups of 8
    const int ng = tid & 15;   // 16 n-groups of 4
    ull acc[8][4] = {};

    auto compute = [&](int buf) {
#pragma unroll
        for (int k4 = 0; k4 < 16; k4 += 4) {
            ulonglong2 w[4];
#pragma unroll
            for (int j = 0; j < 4; j++)
                w[j] = *(const ulonglong2*)&Bs[buf][ng * 4 + j][k4];
#pragma unroll
            for (int i = 0; i < 8; i++) {
                ulonglong2 a = *(const ulonglong2*)&As[buf][mg * 8 + i][k4];
#pragma unroll
                for (int j = 0; j < 4; j++) {
                    ffma2(acc[i][j], a.x, w[j].x);
                    ffma2(acc[i][j], a.y, w[j].y);
                }
            }
        }
    };

    stage(0, 0); cp_commit();
#pragma unroll 1
    for (int s = 0; s < 64; s++) {
        if (s + 1 < 64) { stage((s + 1) & 1, (s + 1) * 16); cp_commit(); cp_wait<1>(); }
        else            { cp_wait<0>(); }
        __syncthreads();
        compute(s & 1);
        __syncthreads();
    }

    const int n = n0 + ng * 4;
#pragma unroll
    for (int i = 0; i < 8; i++) {
        int m = m0 + mg * 8 + i;
        float r[4];
#pragma unroll
        for (int j = 0; j < 4; j++) {
            float lo, hi;
            unpack2(acc[i][j], lo, hi);
            r[j] = lo + hi;
        }
        if (MODE == 0) {
            float4 o = make_float4(r[0] + bias1[n] + bias2[n],
                                   r[1] + bias1[n + 1] + bias2[n + 1],
                                   r[2] + bias1[n + 2] + bias2[n + 2],
                                   r[3] + bias1[n + 3] + bias2[n + 3]);
            *(float4*)&outp[(size_t)m * (4 * H) + n] = o;
        } else {
            int t = m >> 5, b = m & 31;
            float4 o = make_float4(r[0] + bias1[n], r[1] + bias1[n + 1],
                                   r[2] + bias1[n + 2], r[3] + bias1[n + 3]);
            *(float4*)&outp[((size_t)(b * T + t)) * V + n] = o;
        }
    }
}

// ---------------- gates GEMM v3: ctx|h only, K=2048 ------------------------
// grid (32 n-tiles of 128, 32 k-chunks of 64), 128 threads
// per thread 8m x 4n, k-packed f32x2; warp == one m-group (broadcast a-reads)
__global__ void __launch_bounds__(128) k_gates(const float* __restrict__ W_ih,
                                               const float* __restrict__ W_hh) {
    const int n0 = blockIdx.x * 128;
    const int c  = blockIdx.y;      // 0..15: ctx via W_ih right half; 16..31: h via W_hh
    const int tid = threadIdx.x;
    __shared__ float Ws[2][128][20];
    __shared__ float xs[2][32][20];

    const float* W; int ldw, col0, xoff; const float* xsrc;
    if (c < 16) { W = W_ih; ldw = 2 * H; col0 = H + c * 64; xsrc = g_ctx; xoff = c * 64; }
    else        { W = W_hh; ldw = H;     col0 = (c - 16) * 64; xsrc = g_h; xoff = (c - 16) * 64; }

    auto stage = [&](int buf, int k0) {
        // Ws: 128 rows x 16 k = 512 cp16 -> 4 per thread
#pragma unroll
        for (int r = 0; r < 4; r++) {
            int idx = r * 128 + tid;
            int row = idx >> 2, k4 = (idx & 3) * 4;
            cp16(smaddr(&Ws[buf][row][k4]), W + (size_t)(n0 + row) * ldw + col0 + k0 + k4);
        }
        // xs: 32 rows x 16 k = 128 cp16 -> 1 per thread
        if (tid < 128) {
            int row = tid >> 2, k4 = (tid & 3) * 4;
            cp16(smaddr(&xs[buf][row][k4]), xsrc + (size_t)row * H + xoff + k0 + k4);
        }
    };

    const int mg = tid >> 5;   // 4 m-groups of 8 (warp-constant)
    const int ng = tid & 31;   // 32 n-groups of 4
    ull acc[8][4] = {};

    auto compute = [&](int buf) {
#pragma unroll
        for (int k4 = 0; k4 < 16; k4 += 4) {
            ulonglong2 w[4];
#pragma unroll
            for (int j = 0; j < 4; j++)
                w[j] = *(const ulonglong2*)&Ws[buf][ng * 4 + j][k4];
#pragma unroll
            for (int i = 0; i < 8; i++) {
                ulonglong2 a = *(const ulonglong2*)&xs[buf][mg * 8 + i][k4];
#pragma unroll
                for (int j = 0; j < 4; j++) {
                    ffma2(acc[i][j], a.x, w[j].x);
                    ffma2(acc[i][j], a.y, w[j].y);
                }
            }
        }
    };

    stage(0, 0);  cp_commit();
#pragma unroll 1
    for (int s = 0; s < 4; s++) {
        if (s + 1 < 4) { stage((s + 1) & 1, (s + 1) * 16); cp_commit(); cp_wait<1>(); }
        else           { cp_wait<0>(); }
        __syncthreads();
        compute(s & 1);
        __syncthreads();
    }

    float* gp = g_gpart + c * (B * 4 * H);
    const int n = n0 + ng * 4;
#pragma unroll
    for (int i = 0; i < 8; i++) {
        int b = mg * 8 + i;
        float r[4];
#pragma unroll
        for (int j = 0; j < 4; j++) {
            float lo, hi;
            unpack2(acc[i][j], lo, hi);
            r[j] = lo + hi;
        }
        *(float4*)&gp[(size_t)b * 4 * H + n] = make_float4(r[0], r[1], r[2], r[3]);
    }
}

// ---------------- LSTM cell pointwise --------------------------------------
__global__ void k_cell(int t) {
    int idx = blockIdx.x * 256 + threadIdx.x;
    if (idx >= B * H) return;
    int b = idx >> 10, j = idx & (H - 1);
    const float* ge = g_gemb + ((size_t)t * B + b) * (4 * H);
    float gi = ge[j], gf = ge[j + H], gg = ge[j + 2 * H], go = ge[j + 3 * H];
#pragma unroll
    for (int p = 0; p < KG; p++) {
        const float* base = g_gpart + p * (B * 4 * H) + b * 4 * H;
        gi += base[j];
        gf += base[j + H];
        gg += base[j + 2 * H];
        go += base[j + 3 * H];
    }
    float iv = 1.f / (1.f + expf(-gi));
    float fv = 1.f / (1.f + expf(-gf));
    float gv = tanhf(gg);
    float ov = 1.f / (1.f + expf(-go));
    float cn = fv * g_c[idx] + iv * gv;
    float hn = ov * tanhf(cn);
    g_c[idx] = cn;
    g_h[idx] = hn;
    g_Hall[((size_t)t * B + b) * H + j] = hn;
}

// ---------------- final h, c copy ------------------------------------------
__global__ void k_final(float* __restrict__ dst) {
    int i = blockIdx.x * 256 + threadIdx.x;
    if (i < B * H) {
        dst[i]         = g_h[i];
        dst[B * H + i] = g_c[i];
    }
}

} // namespace

extern "C" void kernel_launch(void* const* d_in, const int* in_sizes, int n_in,
                              void* d_out, int out_size) {
    const float* memory   = (const float*)d_in[0];
    const int*   captions = (const int*)d_in[1];
    const float* emb      = (const float*)d_in[2];
    const float* attn_W   = (const float*)d_in[3];
    const float* W_ih     = (const float*)d_in[4];
    const float* W_hh     = (const float*)d_in[5];
    const float* b_ih     = (const float*)d_in[6];
    const float* b_hh     = (const float*)d_in[7];
    const float* W_out    = (const float*)d_in[8];
    const float* b_out    = (const float*)d_in[9];
    float* out = (float*)d_out;

    float* gemb_ptr;
    cudaGetSymbolAddress((void**)&gemb_ptr, g_gemb);

    k_init<<<(B * H + 255) / 256, 256>>>();
    // Precompute emb-side gates for all timesteps: [T*B, 4H] = Emb @ W_ih[:, :H].T
    k_gemm<0><<<dim3((T * B) / 128, (4 * H) / 64), 256>>>(
        W_ih, 2 * H, b_ih, b_hh, gemb_ptr, captions, emb);

    for (int t = 0; t < T; t++) {
        k_q<<<dim3(16, KQ), 256>>>(attn_W);
        k_attn<<<B, 256>>>(memory);
        k_gates<<<dim3(32, KG), 128>>>(W_ih, W_hh);
        k_cell<<<(B * H + 255) / 256, 256>>>(t);
    }
    // Batched logits: Hall[2048,1024] @ W_out.T -> out[B,T,V]
    k_gemm<1><<<dim3((T * B) / 128, V / 64), 256>>>(
        W_out, H, b_out, nullptr, out, nullptr, nullptr);

    if (out_size >= B * T * V + 2 * B * H)
        k_final<<<(B * H + 255) / 256, 256>>>(out + (size_t)B * T * V);
}

// round 4
// speedup vs baseline: 1.6142x; 1.4847x over previous
#include <cuda_runtime.h>
#include <math.h>

namespace {

constexpr int B = 32, S = 196, T = 64, H = 1024, V = 32000;
constexpr int KG = 32;   // gates k-chunks of 64 over K=2048

typedef unsigned long long ull;

// ---------------- device scratch -------------------------------------------
__device__ __align__(16) float g_h[B * H];
__device__ __align__(16) float g_c[B * H];
__device__ __align__(16) float g_ctx[B * H];
__device__ __align__(16) float g_scores[B * 224];
__device__ __align__(16) float g_Wt[H * H];                     // attn_W transposed
__device__ __align__(16) float g_Mw[(size_t)B * S * H];         // memory @ attn_W
__device__ __align__(16) float g_gpart[KG * B * 4 * H];
__device__ __align__(16) float g_gemb[(size_t)T * B * 4 * H];   // emb gates + biases
__device__ __align__(16) float g_Hall[(size_t)T * B * H];       // m = t*B + b

// ---------------- helpers --------------------------------------------------
__device__ __forceinline__ ull pack2(float x, float y) {
    ull r;
    asm("mov.b64 %0, {%1, %2};" : "=l"(r)
        : "r"(__float_as_uint(x)), "r"(__float_as_uint(y)));
    return r;
}
__device__ __forceinline__ void ffma2(ull &d, ull a, ull b) {
    asm("fma.rn.f32x2 %0, %1, %2, %0;" : "+l"(d) : "l"(a), "l"(b));
}
__device__ __forceinline__ void unpack2(ull v, float &x, float &y) {
    unsigned lo, hi;
    asm("mov.b64 {%0, %1}, %2;" : "=r"(lo), "=r"(hi) : "l"(v));
    x = __uint_as_float(lo);
    y = __uint_as_float(hi);
}

// ---------------- init -----------------------------------------------------
__global__ void k_init() {
    int i = blockIdx.x * 256 + threadIdx.x;
    if (i < B * H) { g_h[i] = 0.f; g_c[i] = 0.f; }
}

// ---------------- transpose attn_W -> g_Wt ---------------------------------
__global__ void k_tr(const float* __restrict__ W) {
    __shared__ float tile[32][33];
    int x = blockIdx.x * 32 + threadIdx.x;
    int y0 = blockIdx.y * 32;
    for (int i = threadIdx.y; i < 32; i += 8)
        tile[i][threadIdx.x] = W[(size_t)(y0 + i) * H + x];
    __syncthreads();
    int x2 = blockIdx.y * 32 + threadIdx.x;
    for (int i = threadIdx.y; i < 32; i += 8)
        g_Wt[(size_t)(blockIdx.x * 32 + i) * H + x2] = tile[threadIdx.x][i];
}

// ---------------- unified GEMM core: 128m x 128n, k-major smem -------------
// MODE 0: emb-gates  (A rows = gathered emb, out = g_gemb + b_ih + b_hh)
// MODE 1: logits     (A rows = g_Hall,       out = logits[b,t,:] + b_out)
// MODE 2: Mw         (A rows = memory,       out = g_Mw, no bias)
template <int MODE>
__global__ void __launch_bounds__(256) k_gemm(const float* __restrict__ Bmat, int ldb,
                                              int NS,
                                              const float* __restrict__ bias1,
                                              const float* __restrict__ bias2,
                                              float* __restrict__ outp,
                                              const int* __restrict__ captions,
                                              const float* __restrict__ asrc) {
    const int m0 = blockIdx.x * 128;
    const int n0 = blockIdx.y * 128;
    const int tid = threadIdx.x;
    __shared__ float As[2][16][132];
    __shared__ float Bs[2][16][132];
    __shared__ const float* arow[128];

    if (tid < 128) {
        int m = m0 + tid;
        if (MODE == 0) {
            int t = m >> 5, b = m & 31;
            arow[tid] = asrc + (size_t)captions[b * T + t] * H;
        } else {
            arow[tid] = asrc + (size_t)m * H;
        }
    }
    __syncthreads();

    const int ra = tid >> 2, ka = (tid & 3) * 4;   // ra 0..63
    float4 pa0, pa1, pb0, pb1;
    auto ldg = [&](int k0) {
        pa0 = *(const float4*)(arow[ra] + k0 + ka);
        pa1 = *(const float4*)(arow[ra + 64] + k0 + ka);
        pb0 = *(const float4*)(Bmat + (size_t)(n0 + ra) * ldb + k0 + ka);
        pb1 = *(const float4*)(Bmat + (size_t)(n0 + ra + 64) * ldb + k0 + ka);
    };
    auto sts = [&](int buf) {
        As[buf][ka][ra] = pa0.x; As[buf][ka + 1][ra] = pa0.y;
        As[buf][ka + 2][ra] = pa0.z; As[buf][ka + 3][ra] = pa0.w;
        As[buf][ka][ra + 64] = pa1.x; As[buf][ka + 1][ra + 64] = pa1.y;
        As[buf][ka + 2][ra + 64] = pa1.z; As[buf][ka + 3][ra + 64] = pa1.w;
        Bs[buf][ka][ra] = pb0.x; Bs[buf][ka + 1][ra] = pb0.y;
        Bs[buf][ka + 2][ra] = pb0.z; Bs[buf][ka + 3][ra] = pb0.w;
        Bs[buf][ka][ra + 64] = pb1.x; Bs[buf][ka + 1][ra + 64] = pb1.y;
        Bs[buf][ka + 2][ra + 64] = pb1.z; Bs[buf][ka + 3][ra + 64] = pb1.w;
    };

    const int ty = tid >> 4, tx = tid & 15;   // 16 m-groups of 8, 16 n-groups of 8
    ull acc[8][4] = {};

    ldg(0); sts(0); __syncthreads();
#pragma unroll 1
    for (int s = 0; s < NS; s++) {
        if (s + 1 < NS) ldg((s + 1) * 16);
        const int buf = s & 1;
#pragma unroll
        for (int kk = 0; kk < 16; kk++) {
            float4 a0 = *(const float4*)&As[buf][kk][ty * 8];
            float4 a1 = *(const float4*)&As[buf][kk][ty * 8 + 4];
            ulonglong2 b0 = *(const ulonglong2*)&Bs[buf][kk][tx * 8];
            ulonglong2 b1 = *(const ulonglong2*)&Bs[buf][kk][tx * 8 + 4];
            float av[8] = {a0.x, a0.y, a0.z, a0.w, a1.x, a1.y, a1.z, a1.w};
            ull bp[4] = {b0.x, b0.y, b1.x, b1.y};
#pragma unroll
            for (int i = 0; i < 8; i++) {
                ull ap = pack2(av[i], av[i]);
                ffma2(acc[i][0], ap, bp[0]);
                ffma2(acc[i][1], ap, bp[1]);
                ffma2(acc[i][2], ap, bp[2]);
                ffma2(acc[i][3], ap, bp[3]);
            }
        }
        if (s + 1 < NS) { __syncthreads(); sts((s + 1) & 1); __syncthreads(); }
    }

    const int n = n0 + tx * 8;
#pragma unroll
    for (int i = 0; i < 8; i++) {
        int m = m0 + ty * 8 + i;
        float r[8];
#pragma unroll
        for (int j = 0; j < 4; j++) unpack2(acc[i][j], r[2 * j], r[2 * j + 1]);
        if (MODE == 0) {
#pragma unroll
            for (int u = 0; u < 8; u++) r[u] += bias1[n + u] + bias2[n + u];
            float* o = outp + (size_t)m * (4 * H) + n;
            *(float4*)o = make_float4(r[0], r[1], r[2], r[3]);
            *(float4*)(o + 4) = make_float4(r[4], r[5], r[6], r[7]);
        } else if (MODE == 1) {
#pragma unroll
            for (int u = 0; u < 8; u++) r[u] += bias1[n + u];
            int t = m >> 5, b = m & 31;
            float* o = outp + ((size_t)(b * T + t)) * V + n;
            *(float4*)o = make_float4(r[0], r[1], r[2], r[3]);
            *(float4*)(o + 4) = make_float4(r[4], r[5], r[6], r[7]);
        } else {
            float* o = outp + (size_t)m * H + n;
            *(float4*)o = make_float4(r[0], r[1], r[2], r[3]);
            *(float4*)(o + 4) = make_float4(r[4], r[5], r[6], r[7]);
        }
    }
}

// ---------------- scores: h . Mw[b,s]  grid (B, 7), 256 thr ----------------
__global__ void k_score() {
    const int b = blockIdx.x;
    const int s0 = blockIdx.y * 32;
    const int tid = threadIdx.x;
    __shared__ float hs[H];
    for (int j = tid; j < H; j += 256) hs[j] = g_h[b * H + j];
    __syncthreads();
    const int warp = tid >> 5, lane = tid & 31;
#pragma unroll
    for (int si = 0; si < 4; si++) {
        int s = s0 + si * 8 + warp;
        if (s < S) {
            const float* mw = g_Mw + ((size_t)b * S + s) * H;
            float acc = 0.f;
#pragma unroll 8
            for (int k = lane; k < H; k += 32) acc += hs[k] * mw[k];
#pragma unroll
            for (int o = 16; o; o >>= 1) acc += __shfl_xor_sync(0xffffffffu, acc, o);
            if (lane == 0) g_scores[b * 224 + s] = acc;
        }
    }
}

// ---------------- softmax + ctx: grid (B), 1024 thr ------------------------
__global__ void __launch_bounds__(1024) k_ctx(const float* __restrict__ memory) {
    const int b = blockIdx.x;
    const int tid = threadIdx.x;
    __shared__ float w[224];
    __shared__ float red[1024];

    float sv = (tid < S) ? g_scores[b * 224 + tid] : -1e30f;
    red[tid] = sv;
    __syncthreads();
    for (int st = 512; st; st >>= 1) {
        if (tid < st) red[tid] = fmaxf(red[tid], red[tid + st]);
        __syncthreads();
    }
    float mx = red[0];
    __syncthreads();
    float e = (tid < S) ? expf(sv - mx) : 0.f;
    if (tid < 224) w[tid] = e;
    red[tid] = e;
    __syncthreads();
    for (int st = 512; st; st >>= 1) {
        if (tid < st) red[tid] += red[tid + st];
        __syncthreads();
    }
    float inv = 1.f / red[0];

    const float* mb = memory + (size_t)b * S * H;
    float a = 0.f;
#pragma unroll 1
    for (int s = 0; s < S; s += 4) {
        float w0 = w[s], w1 = w[s + 1], w2 = w[s + 2], w3 = w[s + 3];
        float m0 = mb[(size_t)s * H + tid];
        float m1 = mb[(size_t)(s + 1) * H + tid];
        float m2 = mb[(size_t)(s + 2) * H + tid];
        float m3 = mb[(size_t)(s + 3) * H + tid];
        a += w0 * m0 + w1 * m1 + w2 * m2 + w3 * m3;
    }
    g_ctx[b * H + tid] = a * inv;
}

// ---------------- gates GEMM: 32b x 128n x 64k per block -------------------
// grid (32 n-tiles, 32 k-chunks): c<16 ctx via W_ih right half, c>=16 h via W_hh
__global__ void __launch_bounds__(128) k_gates(const float* __restrict__ W_ih,
                                               const float* __restrict__ W_hh) {
    const int n0 = blockIdx.x * 128;
    const int c  = blockIdx.y;
    const int tid = threadIdx.x;
    __shared__ float Ws[2][16][132];
    __shared__ float xs[2][16][36];

    const float* W; int ldw, col0; const float* xsrc; int xoff;
    if (c < 16) { W = W_ih; ldw = 2 * H; col0 = H + c * 64; xsrc = g_ctx; xoff = c * 64; }
    else        { W = W_hh; ldw = H;     col0 = (c - 16) * 64; xsrc = g_h; xoff = (c - 16) * 64; }

    const int bx = tid >> 2, kx = (tid & 3) * 4;
    float4 px, pw[4];
    auto ldg = [&](int k0) {
        px = *(const float4*)(xsrc + (size_t)bx * H + xoff + k0 + kx);
#pragma unroll
        for (int r = 0; r < 4; r++) {
            int idx = tid + 128 * r;
            int nn = idx >> 2, k4 = (idx & 3) * 4;
            pw[r] = *(const float4*)(W + (size_t)(n0 + nn) * ldw + col0 + k0 + k4);
        }
    };
    auto sts = [&](int buf) {
        xs[buf][kx][bx] = px.x; xs[buf][kx + 1][bx] = px.y;
        xs[buf][kx + 2][bx] = px.z; xs[buf][kx + 3][bx] = px.w;
#pragma unroll
        for (int r = 0; r < 4; r++) {
            int idx = tid + 128 * r;
            int nn = idx >> 2, k4 = (idx & 3) * 4;
            Ws[buf][k4][nn] = pw[r].x; Ws[buf][k4 + 1][nn] = pw[r].y;
            Ws[buf][k4 + 2][nn] = pw[r].z; Ws[buf][k4 + 3][nn] = pw[r].w;
        }
    };

    const int ty = tid >> 4, tx = tid & 15;   // 8 b-groups of 4, 16 n-groups of 8
    ull acc[4][4] = {};

    ldg(0); sts(0); __syncthreads();
#pragma unroll 1
    for (int s = 0; s < 4; s++) {
        if (s + 1 < 4) ldg((s + 1) * 16);
        const int buf = s & 1;
#pragma unroll
        for (int kk = 0; kk < 16; kk++) {
            float4 a = *(const float4*)&xs[buf][kk][ty * 4];
            ulonglong2 w0 = *(const ulonglong2*)&Ws[buf][kk][tx * 8];
            ulonglong2 w1 = *(const ulonglong2*)&Ws[buf][kk][tx * 8 + 4];
            float av[4] = {a.x, a.y, a.z, a.w};
#pragma unroll
            for (int i = 0; i < 4; i++) {
                ull ap = pack2(av[i], av[i]);
                ffma2(acc[i][0], ap, w0.x);
                ffma2(acc[i][1], ap, w0.y);
                ffma2(acc[i][2], ap, w1.x);
                ffma2(acc[i][3], ap, w1.y);
            }
        }
        if (s + 1 < 4) { __syncthreads(); sts((s + 1) & 1); __syncthreads(); }
    }

    float* gp = g_gpart + c * (B * 4 * H);
    const int n = n0 + tx * 8;
#pragma unroll
    for (int i = 0; i < 4; i++) {
        int b = ty * 4 + i;
        float r[8];
#pragma unroll
        for (int j = 0; j < 4; j++) unpack2(acc[i][j], r[2 * j], r[2 * j + 1]);
        float* o = gp + (size_t)b * 4 * H + n;
        *(float4*)o = make_float4(r[0], r[1], r[2], r[3]);
        *(float4*)(o + 4) = make_float4(r[4], r[5], r[6], r[7]);
    }
}

// ---------------- LSTM cell pointwise --------------------------------------
__global__ void k_cell(int t) {
    int idx = blockIdx.x * 256 + threadIdx.x;
    if (idx >= B * H) return;
    int b = idx >> 10, j = idx & (H - 1);
    const float* ge = g_gemb + ((size_t)t * B + b) * (4 * H);
    float gi = ge[j], gf = ge[j + H], gg = ge[j + 2 * H], go = ge[j + 3 * H];
#pragma unroll
    for (int p = 0; p < KG; p++) {
        const float* base = g_gpart + p * (B * 4 * H) + b * 4 * H;
        gi += base[j];
        gf += base[j + H];
        gg += base[j + 2 * H];
        go += base[j + 3 * H];
    }
    float iv = 1.f / (1.f + expf(-gi));
    float fv = 1.f / (1.f + expf(-gf));
    float gv = tanhf(gg);
    float ov = 1.f / (1.f + expf(-go));
    float cn = fv * g_c[idx] + iv * gv;
    float hn = ov * tanhf(cn);
    g_c[idx] = cn;
    g_h[idx] = hn;
    g_Hall[((size_t)t * B + b) * H + j] = hn;
}

// ---------------- final h, c copy ------------------------------------------
__global__ void k_final(float* __restrict__ dst) {
    int i = blockIdx.x * 256 + threadIdx.x;
    if (i < B * H) {
        dst[i]         = g_h[i];
        dst[B * H + i] = g_c[i];
    }
}

} // namespace

extern "C" void kernel_launch(void* const* d_in, const int* in_sizes, int n_in,
                              void* d_out, int out_size) {
    const float* memory   = (const float*)d_in[0];
    const int*   captions = (const int*)d_in[1];
    const float* emb      = (const float*)d_in[2];
    const float* attn_W   = (const float*)d_in[3];
    const float* W_ih     = (const float*)d_in[4];
    const float* W_hh     = (const float*)d_in[5];
    const float* b_ih     = (const float*)d_in[6];
    const float* b_hh     = (const float*)d_in[7];
    const float* W_out    = (const float*)d_in[8];
    const float* b_out    = (const float*)d_in[9];
    float* out = (float*)d_out;

    float *gemb_ptr, *hall_ptr, *mw_ptr, *wt_ptr;
    cudaGetSymbolAddress((void**)&gemb_ptr, g_gemb);
    cudaGetSymbolAddress((void**)&hall_ptr, g_Hall);
    cudaGetSymbolAddress((void**)&mw_ptr, g_Mw);
    cudaGetSymbolAddress((void**)&wt_ptr, g_Wt);

    k_init<<<(B * H + 255) / 256, 256>>>();
    k_tr<<<dim3(32, 32), dim3(32, 8)>>>(attn_W);
    // Mw = memory @ attn_W : [6272, 1024]
    k_gemm<2><<<dim3(B * S / 128, H / 128), 256>>>(
        wt_ptr, H, H / 16, nullptr, nullptr, mw_ptr, nullptr, memory);
    // emb-side gates (+ biases): [2048, 4096]
    k_gemm<0><<<dim3(T * B / 128, 4 * H / 128), 256>>>(
        W_ih, 2 * H, H / 16, b_ih, b_hh, gemb_ptr, captions, emb);

    for (int t = 0; t < T; t++) {
        k_score<<<dim3(B, 7), 256>>>();
        k_ctx<<<B, 1024>>>(memory);
        k_gates<<<dim3(32, KG), 128>>>(W_ih, W_hh);
        k_cell<<<(B * H + 255) / 256, 256>>>(t);
    }

    // logits: Hall[2048,1024] @ W_out.T -> out[B,T,V]
    k_gemm<1><<<dim3(T * B / 128, V / 128), 256>>>(
        W_out, H, H / 16, b_out, nullptr, out, nullptr, hall_ptr);

    if (out_size >= B * T * V + 2 * B * H)
        k_final<<<(B * H + 255) / 256, 256>>>(out + (size_t)B * T * V);
}